// round 11
// baseline (speedup 1.0000x reference)
#include <cuda_runtime.h>
#include <cstdint>

// Problem shape (fixed by the dataset)
#define Bc   8
#define Ac   16384
#define Sc   2048
#define Dc   512
#define OUTc 512
#define CH   16      // residues per pool block

// K-dimension permutation (within each 8-col group): old col c -> position
//   p(c) = (c & ~7) | ((c & 3) << 1) | ((c >> 2) & 1)
// so old pair (lc, lc+4) lands at adjacent positions (2lc, 2lc+1) -> LDS.64 frags.
__host__ __device__ __forceinline__ int kperm(int c) {
    return (c & ~7) | (((c & 3) << 1) | ((c >> 2) & 1));
}

// ---------------- scratch (device globals; no allocation allowed) ----------
__device__ float g_pooled[Bc * Sc * Dc];   // 32 MB pooled [B,S,D], tf32, k-permuted
__device__ float g_Wtf[OUTc * Dc];         // W tf32-rounded, k-permuted
__device__ float g_avgsum[Bc * Dc];        // per-protein sums (k-permuted space)
__device__ int   g_filled[Bc * Sc];
__device__ int   g_nfill[Bc];

// ---------------- helpers --------------------------------------------------
__device__ __forceinline__ float f2tf_f(float x) {
    uint32_t r;
    asm("cvt.rna.tf32.f32 %0, %1;" : "=r"(r) : "f"(x));
    return __uint_as_float(r);
}

#define MMA_TF32(c0, c1, c2, c3, a0, a1, a2, a3, b0, b1)                      \
    asm volatile(                                                             \
        "mma.sync.aligned.m16n8k8.row.col.f32.tf32.tf32.f32 "                 \
        "{%0,%1,%2,%3}, {%4,%5,%6,%7}, {%8,%9}, {%0,%1,%2,%3};"               \
        : "+f"(c0), "+f"(c1), "+f"(c2), "+f"(c3)                              \
        : "r"(a0), "r"(a1), "r"(a2), "r"(a3), "r"(b0), "r"(b1))

__device__ __forceinline__ void cp_async16cg(void* smem_dst, const void* gmem_src) {
    uint32_t dst = (uint32_t)__cvta_generic_to_shared(smem_dst);
    asm volatile("cp.async.cg.shared.global [%0], [%1], 16;" ::"r"(dst), "l"(gmem_src));
}

// ---------------- kernel 0: zero accumulators + convert W to tf32 ----------
__global__ void prep_kernel(const float* __restrict__ W) {
    int i = blockIdx.x * 256 + threadIdx.x;
    if (i < OUTc * Dc) {
        int o = i >> 9, k = i & 511;
        g_Wtf[(o << 9) + kperm(k)] = f2tf_f(W[i]);
    }
    if (i < Bc * Dc) g_avgsum[i] = 0.0f;
    if (i < Bc) g_nfill[i] = 0;
}

// ---------------- kernel 1: fused segment-mean pooling + avg accumulation --
// Processes 4 proteins starting at b0 (chunked for PDL pipelining).
__global__ void pool_kernel(const float* __restrict__ rep,
                            const int* __restrict__ ids,
                            const int* __restrict__ aa_len,
                            const int* __restrict__ seq_len,
                            int b0) {
    const int blk = blockIdx.x;
    const int b = b0 + blk / (Sc / CH);
    const int s0 = (blk % (Sc / CH)) * CH;
    const int L = aa_len[b];
    const int SL = seq_len[b];
    const int* p = ids + b * Ac;

    __shared__ int bound[CH + 1];
    const int t = threadIdx.x;  // 128 threads x 4 cols = 512 cols

    if (t <= CH) {
        int target = s0 + t;
        int lo = 0, hi = L;
        while (lo < hi) { int mid = (lo + hi) >> 1; if (p[mid] < target) lo = mid + 1; else hi = mid; }
        bound[t] = lo;
    }
    __syncthreads();

    // permuted destination columns for this thread's old cols 4t..4t+3
    const int nc0 = kperm(4 * t + 0), nc1 = kperm(4 * t + 1);
    const int nc2 = kperm(4 * t + 2), nc3 = kperm(4 * t + 3);

    const float4* base = reinterpret_cast<const float4*>(rep) + (size_t)b * Ac * (Dc / 4);
    float4 avg = make_float4(0.f, 0.f, 0.f, 0.f);
    int nf_local = 0;

#pragma unroll 1
    for (int i = 0; i < CH; i++) {
        const int st = bound[i], en = bound[i + 1];
        float4 acc = make_float4(0.f, 0.f, 0.f, 0.f);
        int a = st;
        for (; a + 1 < en; a += 2) {
            float4 v0 = base[(size_t)a * (Dc / 4) + t];
            float4 v1 = base[(size_t)(a + 1) * (Dc / 4) + t];
            acc.x += v0.x + v1.x; acc.y += v0.y + v1.y;
            acc.z += v0.z + v1.z; acc.w += v0.w + v1.w;
        }
        if (a < en) {
            float4 v0 = base[(size_t)a * (Dc / 4) + t];
            acc.x += v0.x; acc.y += v0.y; acc.z += v0.z; acc.w += v0.w;
        }
        const int cnt = en - st;
        const float inv = 1.0f / (float)(cnt > 0 ? cnt : 1);
        acc.x = f2tf_f(acc.x * inv); acc.y = f2tf_f(acc.y * inv);
        acc.z = f2tf_f(acc.z * inv); acc.w = f2tf_f(acc.w * inv);

        const int row = b * Sc + s0 + i;
        float* pr = g_pooled + (size_t)row * Dc;
        pr[nc0] = acc.x; pr[nc1] = acc.y; pr[nc2] = acc.z; pr[nc3] = acc.w;

        const bool fill = (cnt > 0) && (s0 + i < SL);
        if (fill) {
            avg.x += acc.x; avg.y += acc.y; avg.z += acc.z; avg.w += acc.w;
            nf_local++;
        }
        if (t == 0) g_filled[row] = fill ? 1 : 0;
    }

    atomicAdd(&g_avgsum[b * Dc + nc0], avg.x);
    atomicAdd(&g_avgsum[b * Dc + nc1], avg.y);
    atomicAdd(&g_avgsum[b * Dc + nc2], avg.z);
    atomicAdd(&g_avgsum[b * Dc + nc3], avg.w);
    if (t == 0) atomicAdd(&g_nfill[b], nf_local);
}

// ---------------- kernel 2: GEMM out = pooled @ W^T + bias (tf32 mma) ------
// M-chunked: 8192 rows per launch. BM=128, BN=64, BK=16, 3-stage, 8 warps.
// Warp tile 32x32 (4x2 warp grid). Reg-capped (<=64) so chunk grids of 512
// CTAs are fully resident AND leave register room for the PDL-overlapped
// pool chunk. Unfilled rows are zero in g_pooled -> output = bias (fixed up
// later by fixup_kernel).
#define BM 128
#define BN 64
#define BK 16
#define PADK 24     // conflict-free for LDS.64 fragment reads (verified per-phase)
#define STG 3
#define GEMM_THREADS 256
#define SMEM_BYTES (STG * (BM + BN) * PADK * 4)

__global__ __launch_bounds__(GEMM_THREADS, 4)
void gemm_kernel(const float* __restrict__ bias, float* __restrict__ out, int bm0) {
#if __CUDA_ARCH__ >= 900
    // Release the PDL-dependent next kernel (pool chunk 1) immediately:
    // it touches no data this kernel produces.
    cudaTriggerProgrammaticLaunchCompletion();
#endif
    extern __shared__ float smem[];
    float* AsBase = smem;                         // [STG][BM][PADK]
    float* BsBase = smem + STG * BM * PADK;       // [STG][BN][PADK]

    const int tid = threadIdx.x;
    const int bm = bm0 + blockIdx.x, bn = blockIdx.y;

    const float* Aori = g_pooled + (size_t)bm * BM * Dc;
    const float* Bori = g_Wtf + (size_t)bn * BN * Dc;

    const int warp = tid >> 5, lane = tid & 31;
    const int wm = warp >> 1, wn = warp & 1;      // 4 x 2 warp grid
    const int m_off = wm * 32, n_off = wn * 32;   // 32x32 warp tile
    const int lr = lane >> 2, lc = lane & 3;

    float c[2][4][4];
#pragma unroll
    for (int mi = 0; mi < 2; mi++)
#pragma unroll
        for (int ni = 0; ni < 4; ni++)
#pragma unroll
            for (int j = 0; j < 4; j++) c[mi][ni][j] = 0.f;

    // A: 128 rows x 4 float4 = 512 chunks -> 2/thread; B: 64 x 4 = 256 -> 1.
    const int a_row = tid >> 2, a_c4 = tid & 3;
    auto load_tile = [&](int kt, int st) {
        const int k0 = kt * BK;
        float* A = AsBase + st * BM * PADK;
        float* B = BsBase + st * BN * PADK;
        cp_async16cg(A + a_row * PADK + a_c4 * 4,
                     Aori + (size_t)a_row * Dc + k0 + a_c4 * 4);
        cp_async16cg(A + (a_row + 64) * PADK + a_c4 * 4,
                     Aori + (size_t)(a_row + 64) * Dc + k0 + a_c4 * 4);
        cp_async16cg(B + a_row * PADK + a_c4 * 4,
                     Bori + (size_t)a_row * Dc + k0 + a_c4 * 4);
        asm volatile("cp.async.commit_group;");
    };

    const int KT = Dc / BK;  // 32
    load_tile(0, 0);
    load_tile(1, 1);

    for (int kt = 0; kt < KT; kt++) {
        asm volatile("cp.async.wait_group 1;");
        __syncthreads();
        if (kt + 2 < KT) load_tile(kt + 2, (kt + 2) % STG);

        const float* A = AsBase + (kt % STG) * BM * PADK;
        const float* B = BsBase + (kt % STG) * BN * PADK;

#pragma unroll
        for (int ks = 0; ks < 2; ks++) {
            const int k0 = ks * 8 + 2 * lc;
            float2 alo[2], ahi[2], bv[4];
#pragma unroll
            for (int mi = 0; mi < 2; mi++) {
                const int r0 = m_off + mi * 16 + lr;
                alo[mi] = *reinterpret_cast<const float2*>(A + r0 * PADK + k0);
                ahi[mi] = *reinterpret_cast<const float2*>(A + (r0 + 8) * PADK + k0);
            }
#pragma unroll
            for (int ni = 0; ni < 4; ni++) {
                const int r0 = n_off + ni * 8 + lr;
                bv[ni] = *reinterpret_cast<const float2*>(B + r0 * PADK + k0);
            }
#pragma unroll
            for (int mi = 0; mi < 2; mi++)
#pragma unroll
                for (int ni = 0; ni < 4; ni++) {
                    MMA_TF32(c[mi][ni][0], c[mi][ni][1], c[mi][ni][2], c[mi][ni][3],
                             __float_as_uint(alo[mi].x), __float_as_uint(ahi[mi].x),
                             __float_as_uint(alo[mi].y), __float_as_uint(ahi[mi].y),
                             __float_as_uint(bv[ni].x), __float_as_uint(bv[ni].y));
                }
        }
        // no trailing sync — STG=3: the stage written by iteration kt+1's load
        // ((kt+3)%3) was consumed in iteration kt-1, ordered by the top barrier.
    }

    // epilogue: + bias, write fp32
    const int row_base = bm * BM + m_off;
    const int col_base = bn * BN + n_off;
#pragma unroll
    for (int mi = 0; mi < 2; mi++) {
#pragma unroll
        for (int ni = 0; ni < 4; ni++) {
            int r0 = row_base + mi * 16 + lr;
            int col = col_base + ni * 8 + 2 * lc;
            float b0 = bias[col], b1 = bias[col + 1];
            float2 v0 = make_float2(c[mi][ni][0] + b0, c[mi][ni][1] + b1);
            float2 v1 = make_float2(c[mi][ni][2] + b0, c[mi][ni][3] + b1);
            *reinterpret_cast<float2*>(out + (size_t)r0 * OUTc + col) = v0;
            *reinterpret_cast<float2*>(out + (size_t)(r0 + 8) * OUTc + col) = v1;
        }
    }
}

// ---------------- kernel 3: fixup unfilled in-range rows in OUT ------------
// out[row] = (avgsum[b]/nfill) @ W^T + bias, fp32. ~1 row per protein.
__global__ void fixup_kernel(const int* __restrict__ seq_len,
                             const float* __restrict__ bias,
                             float* __restrict__ out) {
    const int b = blockIdx.x;
    const int SL = seq_len[b];
    const int t = threadIdx.x;  // 256
    __shared__ float av[Dc];
    __shared__ int rows[256];
    __shared__ int nr;

    const int nf = g_nfill[b];
    const float inv = 1.0f / (float)(nf > 0 ? nf : 1);
    for (int i = t; i < Dc; i += 256) av[i] = g_avgsum[b * Dc + i] * inv;

    for (int tile = 0; tile < Sc; tile += 256) {
        if (t == 0) nr = 0;
        __syncthreads();
        const int s = tile + t;
        if (!g_filled[b * Sc + s] && s < SL) rows[atomicAdd(&nr, 1)] = s;
        __syncthreads();
        for (int i = 0; i < nr; i++) {
            const int r = b * Sc + rows[i];
            int o = t;
#pragma unroll
            for (int h = 0; h < 2; h++, o += 256) {
                const float* w = g_Wtf + (size_t)o * Dc;  // both sides k-permuted
                float acc = 0.f;
                for (int k = 0; k < Dc; k++) acc += av[k] * w[k];
                out[(size_t)r * OUTc + o] = acc + bias[o];
            }
        }
        __syncthreads();
    }
}

// ---------------- launcher -------------------------------------------------
extern "C" void kernel_launch(void* const* d_in, const int* in_sizes, int n_in,
                              void* d_out, int out_size) {
    const float* rep     = (const float*)d_in[0];
    const int*   ids     = (const int*)d_in[1];
    const int*   aa_len  = (const int*)d_in[2];
    const int*   seq_len = (const int*)d_in[3];
    const float* Wm      = (const float*)d_in[4];
    const float* bias    = (const float*)d_in[5];
    float*       out     = (float*)d_out;

    static bool attr_done = false;
    if (!attr_done) {
        cudaFuncSetAttribute(gemm_kernel, cudaFuncAttributeMaxDynamicSharedMemorySize,
                             SMEM_BYTES);
        attr_done = true;
    }

    prep_kernel<<<(OUTc * Dc + 255) / 256, 256>>>(Wm);

    // chunk 0: proteins 0-3
    pool_kernel<<<(Bc / 2) * (Sc / CH), 128>>>(rep, ids, aa_len, seq_len, 0);
    gemm_kernel<<<dim3(64, OUTc / BN), GEMM_THREADS, SMEM_BYTES>>>(bias, out, 0);

    // chunk 1 pool: PDL — released by gemm chunk 0's entry trigger, so it
    // overlaps the tensor-bound GEMM with the DRAM-bound pooling.
    {
        cudaLaunchConfig_t cfg = {};
        cfg.gridDim = dim3((Bc / 2) * (Sc / CH));
        cfg.blockDim = dim3(128);
        cfg.dynamicSmemBytes = 0;
        cudaLaunchAttribute at[1];
        at[0].id = cudaLaunchAttributeProgrammaticStreamSerialization;
        at[0].val.programmaticStreamSerializationAllowed = 1;
        cfg.attrs = at;
        cfg.numAttrs = 1;
        cudaLaunchKernelEx(&cfg, pool_kernel, rep, ids, aa_len, seq_len, (int)(Bc / 2));
    }
    gemm_kernel<<<dim3(64, OUTc / BN), GEMM_THREADS, SMEM_BYTES>>>(bias, out, 64);

    fixup_kernel<<<Bc, 256>>>(seq_len, bias, out);
}